// round 13
// baseline (speedup 1.0000x reference)
#include <cuda_runtime.h>
#include <cuda_bf16.h>
#include <cstdint>

#define N_NODES 100000
#define E_EDGES 1600000
#define IN_C 128
#define OUT_C 64
#define NEG_SLOPE 0.2f
#define EPS 1e-16f

// -------- scratch (device globals; no runtime allocation allowed) --------
__device__ __align__(16) float    g_h[(size_t)N_NODES * OUT_C];   // transformed features
__device__ float    g_ssrc[N_NODES];
__device__ float    g_sdst[N_NODES];
__device__ unsigned g_smax[N_NODES];                // ordered-uint encoded max
__device__ float    g_denom[N_NODES];
__device__ float    g_elog[E_EDGES + N_NODES];      // logits, then exp values
__device__ __align__(16) int g_src[E_EDGES];
__device__ __align__(16) int g_dst[E_EDGES];
__device__ unsigned g_hi_or;                        // dtype probe accumulator

// monotone float<->uint encoding for atomicMax over signed floats
__device__ __forceinline__ unsigned f2o(float f) {
    unsigned u = __float_as_uint(f);
    return (u & 0x80000000u) ? ~u : (u | 0x80000000u);
}
__device__ __forceinline__ float o2f(unsigned u) {
    unsigned b = (u & 0x80000000u) ? (u & 0x7fffffffu) : ~u;
    return __uint_as_float(b);
}

// -------- K0: init out / smax / denom / probe flag --------
__global__ void init_kernel(float* __restrict__ out, int N) {
    int i = blockIdx.x * blockDim.x + threadIdx.x;
    if (i < N * OUT_C) out[i] = 0.0f;
    if (i < N) { g_smax[i] = 0u; g_denom[i] = 0.0f; }
    if (i == 0) g_hi_or = 0u;
}

// -------- K0b: probe edge-index dtype --------
// If buffer is int64 (values < 2^31, nonneg), every odd 32-bit word in the
// first 2048 words is the zero high-half. If int32, those words are real
// src indices (random in [0,100000)) — OR is nonzero w.p. ~1.
__global__ void detect_kernel(const unsigned* __restrict__ ei32) {
    int i = blockIdx.x * blockDim.x + threadIdx.x;   // 1024 threads
    unsigned v = ei32[2 * i + 1];
    #pragma unroll
    for (int off = 16; off > 0; off >>= 1)
        v |= __shfl_xor_sync(0xffffffffu, v, off);
    if ((threadIdx.x & 31) == 0 && v) atomicOr(&g_hi_or, v);
}

// -------- K0c: normalize edges into int32 src/dst --------
__global__ void convert_kernel(const void* __restrict__ ei, int E) {
    int i = blockIdx.x * blockDim.x + threadIdx.x;
    if (i >= E) return;
    if (g_hi_or == 0u) {  // int64 layout
        const long long* p = (const long long*)ei;
        g_src[i] = (int)p[i];
        g_dst[i] = (int)p[(size_t)E + i];
    } else {              // int32 layout
        const int* p = (const int*)ei;
        g_src[i] = p[i];
        g_dst[i] = p[E + i];
    }
}

// -------- K1: h = x @ W, fused s_src = h.a_src, s_dst = h.a_dst --------
// 256 threads/block, 128 nodes/block. Each thread: 4 nodes x 8 contiguous cols.
__global__ __launch_bounds__(256) void gemm_kernel(
    const float* __restrict__ x, const float* __restrict__ W,
    const float* __restrict__ a_src, const float* __restrict__ a_dst, int N)
{
    __shared__ float xs[128][33];                     // scalar access only
    __shared__ __align__(16) float ws[32][OUT_C];     // float4 access

    const int tid = threadIdx.x;
    const int t = tid & 7;             // 0..7 : which 8-col slice
    const int group = tid >> 3;        // 0..31 : which 4-node group
    const int nodeBase = blockIdx.x * 128;

    float acc[4][8];
    #pragma unroll
    for (int m = 0; m < 4; m++)
        #pragma unroll
        for (int j = 0; j < 8; j++) acc[m][j] = 0.0f;

    for (int kc = 0; kc < IN_C; kc += 32) {
        __syncthreads();
        #pragma unroll
        for (int r = 0; r < 4; r++) {
            int i = tid + r * 256;
            int nl = i >> 3, f4 = i & 7;
            int gn = nodeBase + nl;
            float4 v = make_float4(0.f, 0.f, 0.f, 0.f);
            if (gn < N) v = *(const float4*)(x + (size_t)gn * IN_C + kc + f4 * 4);
            xs[nl][f4 * 4 + 0] = v.x; xs[nl][f4 * 4 + 1] = v.y;
            xs[nl][f4 * 4 + 2] = v.z; xs[nl][f4 * 4 + 3] = v.w;
        }
        #pragma unroll
        for (int r = 0; r < 2; r++) {
            int i = tid + r * 256;
            int kk = i >> 4, c = (i & 15) * 4;
            *(float4*)&ws[kk][c] = *(const float4*)(W + (size_t)(kc + kk) * OUT_C + c);
        }
        __syncthreads();
        #pragma unroll
        for (int k = 0; k < 32; k++) {
            float4 w0 = *(float4*)&ws[k][t * 8];
            float4 w1 = *(float4*)&ws[k][t * 8 + 4];
            #pragma unroll
            for (int m = 0; m < 4; m++) {
                float xv = xs[group * 4 + m][k];
                acc[m][0] += xv * w0.x; acc[m][1] += xv * w0.y;
                acc[m][2] += xv * w0.z; acc[m][3] += xv * w0.w;
                acc[m][4] += xv * w1.x; acc[m][5] += xv * w1.y;
                acc[m][6] += xv * w1.z; acc[m][7] += xv * w1.w;
            }
        }
    }

    float as[8], ad[8];
    #pragma unroll
    for (int j = 0; j < 8; j++) { as[j] = a_src[t * 8 + j]; ad[j] = a_dst[t * 8 + j]; }

    #pragma unroll
    for (int m = 0; m < 4; m++) {
        int node = nodeBase + group * 4 + m;
        float ps = 0.f, pd = 0.f;
        #pragma unroll
        for (int j = 0; j < 8; j++) { ps += acc[m][j] * as[j]; pd += acc[m][j] * ad[j]; }
        #pragma unroll
        for (int off = 4; off > 0; off >>= 1) {
            ps += __shfl_xor_sync(0xffffffffu, ps, off);
            pd += __shfl_xor_sync(0xffffffffu, pd, off);
        }
        if (node < N) {
            *(float4*)(g_h + (size_t)node * OUT_C + t * 8) =
                make_float4(acc[m][0], acc[m][1], acc[m][2], acc[m][3]);
            *(float4*)(g_h + (size_t)node * OUT_C + t * 8 + 4) =
                make_float4(acc[m][4], acc[m][5], acc[m][6], acc[m][7]);
            if (t == 0) { g_ssrc[node] = ps; g_sdst[node] = pd; }
        }
    }
}

// -------- K2: per-edge logits + segment max --------
__global__ void logits_kernel(int E, int N) {
    int i = blockIdx.x * blockDim.x + threadIdx.x;
    if (i >= E + N) return;
    int s, d;
    if (i < E) { s = g_src[i]; d = g_dst[i]; }
    else { s = i - E; d = s; }
    float l = g_ssrc[s] + g_sdst[d];
    l = l > 0.0f ? l : NEG_SLOPE * l;
    g_elog[i] = l;
    atomicMax(&g_smax[d], f2o(l));
}

// -------- K3: e = exp(logit - max), segment sum --------
__global__ void denom_kernel(int E, int N) {
    int i = blockIdx.x * blockDim.x + threadIdx.x;
    if (i >= E + N) return;
    int d = (i < E) ? g_dst[i] : (i - E);
    float e = __expf(g_elog[i] - o2f(g_smax[d]));
    g_elog[i] = e;
    atomicAdd(&g_denom[d], e);
}

// -------- K4: weighted scatter of messages (16 threads / edge, v4 red) --------
__global__ void scatter_kernel(int E, int N, float* __restrict__ out) {
    int gt = blockIdx.x * blockDim.x + threadIdx.x;
    int i = gt >> 4;
    int c = (gt & 15) << 2;
    if (i >= E + N) return;
    int s, d;
    if (i < E) { s = g_src[i]; d = g_dst[i]; }
    else { s = i - E; d = s; }
    float coef = g_elog[i] / (g_denom[d] + EPS);
    float4 hv = *(const float4*)(g_h + (size_t)s * OUT_C + c);
    float* p = out + (size_t)d * OUT_C + c;
    asm volatile("red.global.add.v4.f32 [%0], {%1,%2,%3,%4};"
                 :: "l"(p), "f"(coef * hv.x), "f"(coef * hv.y),
                    "f"(coef * hv.z), "f"(coef * hv.w)
                 : "memory");
}

// -------- K5: out = elu(out + b) --------
__global__ void finalize_kernel(float* __restrict__ out, const float* __restrict__ b, int N) {
    int i = blockIdx.x * blockDim.x + threadIdx.x;
    if (i >= N * OUT_C) return;
    float v = out[i] + __ldg(&b[i & (OUT_C - 1)]);
    out[i] = v > 0.0f ? v : expm1f(v);
}

extern "C" void kernel_launch(void* const* d_in, const int* in_sizes, int n_in,
                              void* d_out, int out_size) {
    const float* x     = (const float*)d_in[0];
    const void*  ei    = d_in[1];
    const float* W     = (const float*)d_in[2];
    const float* a_src = (const float*)d_in[3];
    const float* a_dst = (const float*)d_in[4];
    const float* b     = (const float*)d_in[5];
    float*       out   = (float*)d_out;

    int N = in_sizes[0] / IN_C;      // 100000
    int E = in_sizes[1] / 2;         // 1600000
    int T = E + N;

    init_kernel<<<(N * OUT_C + 511) / 512, 512>>>(out, N);
    detect_kernel<<<4, 256>>>((const unsigned*)ei);
    convert_kernel<<<(E + 255) / 256, 256>>>(ei, E);
    gemm_kernel<<<(N + 127) / 128, 256>>>(x, W, a_src, a_dst, N);
    logits_kernel<<<(T + 255) / 256, 256>>>(E, N);
    denom_kernel<<<(T + 255) / 256, 256>>>(E, N);
    {
        long long total = (long long)T * 16;
        int blocks = (int)((total + 255) / 256);
        scatter_kernel<<<blocks, 256>>>(E, N, out);
    }
    finalize_kernel<<<(N * OUT_C + 255) / 256, 256>>>(out, b, N);
}

// round 14
// speedup vs baseline: 1.3443x; 1.3443x over previous
#include <cuda_runtime.h>
#include <cuda_bf16.h>
#include <cstdint>

#define N_NODES 100000
#define E_EDGES 1600000
#define IN_C 128
#define OUT_C 64
#define NEG_SLOPE 0.2f
#define EPS 1e-16f

// -------- scratch (device globals; no runtime allocation allowed) --------
__device__ __align__(16) float g_h[(size_t)N_NODES * OUT_C];  // transformed features
__device__ float    g_ssrc[N_NODES];
__device__ float    g_sdst[N_NODES];
__device__ __align__(16) int g_src[E_EDGES];
__device__ __align__(16) int g_dst[E_EDGES];
__device__ int      g_csr_src[E_EDGES];     // src indices sorted by dst bucket
__device__ int      g_cnt[N_NODES];         // in-degree histogram
__device__ int      g_ptr[N_NODES + 1];     // CSR row pointers
__device__ int      g_cur[N_NODES];         // scatter cursors
__device__ int      g_bsum[1024];           // per-block sums for scan
__device__ unsigned g_hi_or;                // dtype probe accumulator

__device__ __forceinline__ float leaky(float l) {
    return l > 0.0f ? l : NEG_SLOPE * l;
}

// -------- K0: zero histogram + probe flag --------
__global__ void init_kernel(int N) {
    int i = blockIdx.x * blockDim.x + threadIdx.x;
    if (i < N) g_cnt[i] = 0;
    if (i == 0) g_hi_or = 0u;
}

// -------- K0b: probe edge-index dtype (int64 vs int32) --------
__global__ void detect_kernel(const unsigned* __restrict__ ei32) {
    int i = blockIdx.x * blockDim.x + threadIdx.x;   // 1024 threads
    unsigned v = ei32[2 * i + 1];
    #pragma unroll
    for (int off = 16; off > 0; off >>= 1)
        v |= __shfl_xor_sync(0xffffffffu, v, off);
    if ((threadIdx.x & 31) == 0 && v) atomicOr(&g_hi_or, v);
}

// -------- K0c: normalize edges into int32 src/dst --------
__global__ void convert_kernel(const void* __restrict__ ei, int E) {
    int i = blockIdx.x * blockDim.x + threadIdx.x;
    if (i >= E) return;
    if (g_hi_or == 0u) {  // int64 layout
        const long long* p = (const long long*)ei;
        g_src[i] = (int)p[i];
        g_dst[i] = (int)p[(size_t)E + i];
    } else {              // int32 layout
        const int* p = (const int*)ei;
        g_src[i] = p[i];
        g_dst[i] = p[E + i];
    }
}

// -------- K1: h = x @ W, fused s_src = h.a_src, s_dst = h.a_dst --------
__global__ __launch_bounds__(256) void gemm_kernel(
    const float* __restrict__ x, const float* __restrict__ W,
    const float* __restrict__ a_src, const float* __restrict__ a_dst, int N)
{
    __shared__ float xs[128][33];
    __shared__ __align__(16) float ws[32][OUT_C];

    const int tid = threadIdx.x;
    const int t = tid & 7;
    const int group = tid >> 3;
    const int nodeBase = blockIdx.x * 128;

    float acc[4][8];
    #pragma unroll
    for (int m = 0; m < 4; m++)
        #pragma unroll
        for (int j = 0; j < 8; j++) acc[m][j] = 0.0f;

    for (int kc = 0; kc < IN_C; kc += 32) {
        __syncthreads();
        #pragma unroll
        for (int r = 0; r < 4; r++) {
            int i = tid + r * 256;
            int nl = i >> 3, f4 = i & 7;
            int gn = nodeBase + nl;
            float4 v = make_float4(0.f, 0.f, 0.f, 0.f);
            if (gn < N) v = *(const float4*)(x + (size_t)gn * IN_C + kc + f4 * 4);
            xs[nl][f4 * 4 + 0] = v.x; xs[nl][f4 * 4 + 1] = v.y;
            xs[nl][f4 * 4 + 2] = v.z; xs[nl][f4 * 4 + 3] = v.w;
        }
        #pragma unroll
        for (int r = 0; r < 2; r++) {
            int i = tid + r * 256;
            int kk = i >> 4, c = (i & 15) * 4;
            *(float4*)&ws[kk][c] = *(const float4*)(W + (size_t)(kc + kk) * OUT_C + c);
        }
        __syncthreads();
        #pragma unroll
        for (int k = 0; k < 32; k++) {
            float4 w0 = *(float4*)&ws[k][t * 8];
            float4 w1 = *(float4*)&ws[k][t * 8 + 4];
            #pragma unroll
            for (int m = 0; m < 4; m++) {
                float xv = xs[group * 4 + m][k];
                acc[m][0] += xv * w0.x; acc[m][1] += xv * w0.y;
                acc[m][2] += xv * w0.z; acc[m][3] += xv * w0.w;
                acc[m][4] += xv * w1.x; acc[m][5] += xv * w1.y;
                acc[m][6] += xv * w1.z; acc[m][7] += xv * w1.w;
            }
        }
    }

    float as[8], ad[8];
    #pragma unroll
    for (int j = 0; j < 8; j++) { as[j] = a_src[t * 8 + j]; ad[j] = a_dst[t * 8 + j]; }

    #pragma unroll
    for (int m = 0; m < 4; m++) {
        int node = nodeBase + group * 4 + m;
        float ps = 0.f, pd = 0.f;
        #pragma unroll
        for (int j = 0; j < 8; j++) { ps += acc[m][j] * as[j]; pd += acc[m][j] * ad[j]; }
        #pragma unroll
        for (int off = 4; off > 0; off >>= 1) {
            ps += __shfl_xor_sync(0xffffffffu, ps, off);
            pd += __shfl_xor_sync(0xffffffffu, pd, off);
        }
        if (node < N) {
            *(float4*)(g_h + (size_t)node * OUT_C + t * 8) =
                make_float4(acc[m][0], acc[m][1], acc[m][2], acc[m][3]);
            *(float4*)(g_h + (size_t)node * OUT_C + t * 8 + 4) =
                make_float4(acc[m][4], acc[m][5], acc[m][6], acc[m][7]);
            if (t == 0) { g_ssrc[node] = ps; g_sdst[node] = pd; }
        }
    }
}

// -------- K2: in-degree histogram --------
__global__ void hist_kernel(int E) {
    int i = blockIdx.x * blockDim.x + threadIdx.x;
    if (i < E) atomicAdd(&g_cnt[g_dst[i]], 1);
}

// -------- K3a: per-block sums of g_cnt --------
__global__ __launch_bounds__(256) void bsum_kernel(int N) {
    int i = blockIdx.x * 256 + threadIdx.x;
    int v = (i < N) ? g_cnt[i] : 0;
    #pragma unroll
    for (int off = 16; off > 0; off >>= 1)
        v += __shfl_xor_sync(0xffffffffu, v, off);
    __shared__ int sh[8];
    int lane = threadIdx.x & 31, wid = threadIdx.x >> 5;
    if (lane == 0) sh[wid] = v;
    __syncthreads();
    if (wid == 0) {
        int s = (lane < 8) ? sh[lane] : 0;
        #pragma unroll
        for (int off = 4; off > 0; off >>= 1)
            s += __shfl_xor_sync(0xffffffffu, s, off);
        if (lane == 0) g_bsum[blockIdx.x] = s;
    }
}

// -------- K3b: exclusive scan of block sums (nb <= 512, one block) --------
__global__ __launch_bounds__(512) void bscan_kernel(int nb, int N) {
    int tid = threadIdx.x, lane = tid & 31, wid = tid >> 5;
    int v = (tid < nb) ? g_bsum[tid] : 0;
    int x = v;
    #pragma unroll
    for (int off = 1; off < 32; off <<= 1) {
        int t = __shfl_up_sync(0xffffffffu, x, off);
        if (lane >= off) x += t;
    }
    __shared__ int sh[16];
    if (lane == 31) sh[wid] = x;
    __syncthreads();
    if (wid == 0) {
        int y = (lane < 16) ? sh[lane] : 0;
        #pragma unroll
        for (int off = 1; off < 16; off <<= 1) {
            int t = __shfl_up_sync(0xffffffffu, y, off);
            if (lane >= off) y += t;
        }
        if (lane < 16) sh[lane] = y;
    }
    __syncthreads();
    int excl = x - v + (wid > 0 ? sh[wid - 1] : 0);
    if (tid < nb) g_bsum[tid] = excl;
    if (tid == 0) g_ptr[N] = sh[15];   // total edge count
}

// -------- K3c: per-block rescan -> row pointers + cursors --------
__global__ __launch_bounds__(256) void rescan_kernel(int N) {
    int tid = threadIdx.x, lane = tid & 31, wid = tid >> 5;
    int i = blockIdx.x * 256 + tid;
    int v = (i < N) ? g_cnt[i] : 0;
    int x = v;
    #pragma unroll
    for (int off = 1; off < 32; off <<= 1) {
        int t = __shfl_up_sync(0xffffffffu, x, off);
        if (lane >= off) x += t;
    }
    __shared__ int sh[8];
    if (lane == 31) sh[wid] = x;
    __syncthreads();
    if (wid == 0) {
        int y = (lane < 8) ? sh[lane] : 0;
        #pragma unroll
        for (int off = 1; off < 8; off <<= 1) {
            int t = __shfl_up_sync(0xffffffffu, y, off);
            if (lane >= off) y += t;
        }
        if (lane < 8) sh[lane] = y;
    }
    __syncthreads();
    int excl = x - v + (wid > 0 ? sh[wid - 1] : 0) + g_bsum[blockIdx.x];
    if (i < N) { g_ptr[i] = excl; g_cur[i] = excl; }
}

// -------- K4: scatter edges into CSR buckets --------
__global__ void csr_kernel(int E) {
    int i = blockIdx.x * blockDim.x + threadIdx.x;
    if (i >= E) return;
    int d = g_dst[i];
    int pos = atomicAdd(&g_cur[d], 1);
    g_csr_src[pos] = g_src[i];
}

// -------- K5: per-node aggregation (one warp per dst node, no atomics) ----
// online softmax over incoming edges + self-loop, then register-accumulated
// weighted gather of h[src], bias + ELU fused.
__global__ __launch_bounds__(256) void agg_kernel(
    float* __restrict__ out, const float* __restrict__ b, int N)
{
    int d = (blockIdx.x * blockDim.x + threadIdx.x) >> 5;
    int lane = threadIdx.x & 31;
    if (d >= N) return;

    int begin = g_ptr[d], end = g_ptr[d + 1];
    float sd = g_sdst[d];
    float l_self = leaky(g_ssrc[d] + sd);

    // ---- pass 1: online (max, sum) over edges; M seeded at l_self ----
    float M = l_self, S = 0.0f;
    for (int e = begin + lane; e < end; e += 32) {
        int s = g_csr_src[e];
        float l = leaky(g_ssrc[s] + sd);
        float Mn = fmaxf(M, l);
        S = S * __expf(M - Mn) + __expf(l - Mn);
        M = Mn;
    }
    // warp merge of (M, S)
    #pragma unroll
    for (int off = 16; off > 0; off >>= 1) {
        float Mo = __shfl_xor_sync(0xffffffffu, M, off);
        float So = __shfl_xor_sync(0xffffffffu, S, off);
        float Mn = fmaxf(M, Mo);
        S = S * __expf(M - Mn) + So * __expf(Mo - Mn);
        M = Mn;
    }
    S += __expf(l_self - M);            // self-loop contribution
    float invS = 1.0f / (S + EPS);

    // ---- pass 2: weighted gather; each lane owns 2 output columns ----
    float2 acc;
    {
        float cs = __expf(l_self - M) * invS;
        float2 hv = *(const float2*)(g_h + (size_t)d * OUT_C + lane * 2);
        acc.x = cs * hv.x; acc.y = cs * hv.y;
    }
    for (int eb = begin; eb < end; eb += 32) {
        int e = eb + lane;
        float coef = 0.0f; int s = 0;
        if (e < end) {
            s = g_csr_src[e];
            float l = leaky(g_ssrc[s] + sd);
            coef = __expf(l - M) * invS;
        }
        int cnt = min(32, end - eb);
        for (int j = 0; j < cnt; ++j) {
            float c = __shfl_sync(0xffffffffu, coef, j);
            int sj  = __shfl_sync(0xffffffffu, s, j);
            float2 hv = *(const float2*)(g_h + (size_t)sj * OUT_C + lane * 2);
            acc.x += c * hv.x; acc.y += c * hv.y;
        }
    }

    // ---- bias + ELU, write out ----
    float2 bb = *(const float2*)(b + lane * 2);
    float v0 = acc.x + bb.x, v1 = acc.y + bb.y;
    v0 = v0 > 0.0f ? v0 : expm1f(v0);
    v1 = v1 > 0.0f ? v1 : expm1f(v1);
    *(float2*)(out + (size_t)d * OUT_C + lane * 2) = make_float2(v0, v1);
}

extern "C" void kernel_launch(void* const* d_in, const int* in_sizes, int n_in,
                              void* d_out, int out_size) {
    const float* x     = (const float*)d_in[0];
    const void*  ei    = d_in[1];
    const float* W     = (const float*)d_in[2];
    const float* a_src = (const float*)d_in[3];
    const float* a_dst = (const float*)d_in[4];
    const float* b     = (const float*)d_in[5];
    float*       out   = (float*)d_out;

    int N = in_sizes[0] / IN_C;      // 100000
    int E = in_sizes[1] / 2;         // 1600000
    int nb = (N + 255) / 256;        // 391 scan blocks (<= 512)

    init_kernel<<<(N + 255) / 256, 256>>>(N);
    detect_kernel<<<4, 256>>>((const unsigned*)ei);
    convert_kernel<<<(E + 255) / 256, 256>>>(ei, E);
    gemm_kernel<<<(N + 127) / 128, 256>>>(x, W, a_src, a_dst, N);
    hist_kernel<<<(E + 255) / 256, 256>>>(E);
    bsum_kernel<<<nb, 256>>>(N);
    bscan_kernel<<<1, 512>>>(nb, N);
    rescan_kernel<<<nb, 256>>>(N);
    csr_kernel<<<(E + 255) / 256, 256>>>(E);
    agg_kernel<<<(N * 32 + 255) / 256, 256>>>(out, b, N);
}